// round 14
// baseline (speedup 1.0000x reference)
#include <cuda_runtime.h>
#include <cstdint>

#define TDIM 2048
#define CB 4
#define HN 12
#define HD 64
#define BH (CB*HN)
#define CEMB 768
#define N3C 2304

// ---- attention smem (3-stage) ----
#define KVS 72                             // smem row stride (floats)
#define TILE_F (64 * KVS)                  // 4608
#define BUF_F (2 * TILE_F)                 // K + V, one stage = 9216 floats
#define ATTN_SMEM (3 * BUF_F * 4)          // 110592 B

// ---- qkv mma smem (K-tile 16, hi/lo interleaved, 3-stage) ----
#define SAQ 40                             // A row stride: 32 data + 8 pad
#define SBW 264                            // W row stride: 256 data + 8 pad
#define QSTAGE (128*SAQ + 16*SBW)          // 9344 floats per stage
#define QKV_SMEM (3 * QSTAGE * 4)          // 112128 B

#define NX (8192 * CEMB)
#define NW (CEMB * N3C)

// Pre-split inputs: interleaved (hi,lo) tf32 pairs.
__device__ __align__(16) float g_xs[(size_t)NX * 2];
__device__ __align__(16) float g_ws[(size_t)NW * 2];

// q: (B,H,T,D) plain. k: (B,H,T,D) with D permuted [0,4,1,5,2,6,3,7] per
// 8-group. v: (B,H,D,T) transposed, T permuted the same way per 8-group.
__device__ __align__(16) float g_q[(size_t)BH * TDIM * HD];
__device__ __align__(16) float g_k[(size_t)BH * TDIM * HD];
__device__ __align__(16) float g_vt[(size_t)BH * HD * TDIM];

__device__ __forceinline__ int perm8(int u) { return ((u & 3) << 1) | ((u >> 2) & 1); }
__device__ __forceinline__ int permd(int d) { return (d & ~7) | perm8(d & 7); }

__device__ __forceinline__ uint32_t f2tf32(float x) {
    uint32_t u;
    asm("cvt.rna.tf32.f32 %0, %1;" : "=r"(u) : "f"(x));
    return u;
}

__device__ __forceinline__ void mma_tf32(float& d0, float& d1, float& d2, float& d3,
                                         uint32_t a0, uint32_t a1, uint32_t a2, uint32_t a3,
                                         uint32_t b0, uint32_t b1) {
    asm volatile("mma.sync.aligned.m16n8k8.row.col.f32.tf32.tf32.f32 "
                 "{%0,%1,%2,%3}, {%4,%5,%6,%7}, {%8,%9}, {%0,%1,%2,%3};"
                 : "+f"(d0), "+f"(d1), "+f"(d2), "+f"(d3)
                 : "r"(a0), "r"(a1), "r"(a2), "r"(a3), "r"(b0), "r"(b1));
}

__device__ __forceinline__ void cpa16(uint32_t dst, const float* src) {
    asm volatile("cp.async.cg.shared.global [%0], [%1], 16;" :: "r"(dst), "l"(src));
}

// ---------------------------------------------------------------------------
// Kernel 0: split x and W into interleaved tf32 (hi, lo) pairs.
// ---------------------------------------------------------------------------
__global__ __launch_bounds__(256)
void split_kernel(const float* __restrict__ x, const float* __restrict__ w)
{
    const int i = blockIdx.x * blockDim.x + threadIdx.x;
    if (i < NX) {
        const float v = x[i];
        const uint32_t hi = f2tf32(v);
        const uint32_t lo = f2tf32(v - __uint_as_float(hi));
        *(float2*)&g_xs[(size_t)i * 2] =
            make_float2(__uint_as_float(hi), __uint_as_float(lo));
    }
    const int j = i - NX;
    if (j >= 0 && j < NW) {
        const float v = w[j];
        const uint32_t hi = f2tf32(v);
        const uint32_t lo = f2tf32(v - __uint_as_float(hi));
        *(float2*)&g_ws[(size_t)j * 2] =
            make_float2(__uint_as_float(hi), __uint_as_float(lo));
    }
}

// ---------------------------------------------------------------------------
// Kernel 1: QKV GEMM, 3xTF32 with pre-split operands. 128x128 block tile,
// K-tile 16, 8 warps each 64x32, THREE-stage cp.async pipeline with ONE
// barrier per k-tile (overwrite target is 2 stages back).
// ---------------------------------------------------------------------------
__global__ __launch_bounds__(256, 2)
void qkv_mma_kernel(const float* __restrict__ bias)
{
    extern __shared__ __align__(16) float sm[];

    const int tid  = threadIdx.x;
    const int w    = tid >> 5;
    const int lane = tid & 31;
    const int p    = lane & 3;
    const int q    = lane >> 2;
    const int wm   = w >> 2;          // 0..1  (64-row slab)
    const int wn   = w & 3;           // 0..3  (32-col slab)

    const int m0 = blockIdx.y << 7;
    const int n0 = blockIdx.x << 7;

    const uint32_t smu = (uint32_t)__cvta_generic_to_shared(sm);

    float acc[4][4][4];
    #pragma unroll
    for (int mi = 0; mi < 4; mi++)
        #pragma unroll
        for (int g = 0; g < 4; g++)
            #pragma unroll
            for (int r = 0; r < 4; r++)
                acc[mi][g][r] = 0.0f;

    // stage loader: per thread 4 float4 for A, 4 for W.
    auto load_stage = [&](int kt, int sbuf) {
        const int kb = kt << 4;
        const uint32_t sb = smu + (uint32_t)(sbuf * QSTAGE) * 4;
        #pragma unroll
        for (int i = 0; i < 4; i++) {
            const int idx = tid + (i << 8);
            const int arow = idx >> 3, acol = (idx & 7) << 2;     // A: 32 f/row
            const int krow = idx >> 6, wcol = (idx & 63) << 2;    // W: 256 f/row
            cpa16(sb + (uint32_t)(arow * SAQ + acol) * 4,
                  g_xs + (size_t)(m0 + arow) * (CEMB * 2) + kb * 2 + acol);
            cpa16(sb + (uint32_t)(128 * SAQ + krow * SBW + wcol) * 4,
                  g_ws + (size_t)(kb + krow) * (N3C * 2) + n0 * 2 + wcol);
        }
        asm volatile("cp.async.commit_group;");
    };

    // prologue: stages 0 and 1
    load_stage(0, 0);
    load_stage(1, 1);

    int cbuf = 0, lbuf = 2;
    for (int kt = 0; kt < 48; kt++) {
        if (kt < 47) asm volatile("cp.async.wait_group 1;");
        else         asm volatile("cp.async.wait_group 0;");
        __syncthreads();

        if (kt + 2 < 48) {
            load_stage(kt + 2, lbuf);
            lbuf = (lbuf == 2) ? 0 : lbuf + 1;
        }

        const float* As = sm + cbuf * QSTAGE;
        const float* Ws = As + 128 * SAQ;
        cbuf = (cbuf == 2) ? 0 : cbuf + 1;

        #pragma unroll
        for (int kc = 0; kc < 16; kc += 8) {
            uint32_t ah[4][4], al[4][4], bh[4][2], bl[4][2];
            #pragma unroll
            for (int mi = 0; mi < 4; mi++) {
                const int base = (wm * 64 + mi * 16 + q) * SAQ + ((kc + p) << 1);
                const float2 f0 = *(const float2*)&As[base];
                const float2 f1 = *(const float2*)&As[base + 8 * SAQ];
                const float2 f2 = *(const float2*)&As[base + 8];
                const float2 f3 = *(const float2*)&As[base + 8 * SAQ + 8];
                ah[mi][0] = __float_as_uint(f0.x); al[mi][0] = __float_as_uint(f0.y);
                ah[mi][1] = __float_as_uint(f1.x); al[mi][1] = __float_as_uint(f1.y);
                ah[mi][2] = __float_as_uint(f2.x); al[mi][2] = __float_as_uint(f2.y);
                ah[mi][3] = __float_as_uint(f3.x); al[mi][3] = __float_as_uint(f3.y);
            }
            #pragma unroll
            for (int g = 0; g < 4; g++) {
                const int bb = (kc + p) * SBW + ((wn * 32 + g * 8 + q) << 1);
                const float2 w0 = *(const float2*)&Ws[bb];
                const float2 w1 = *(const float2*)&Ws[bb + 4 * SBW];
                bh[g][0] = __float_as_uint(w0.x); bl[g][0] = __float_as_uint(w0.y);
                bh[g][1] = __float_as_uint(w1.x); bl[g][1] = __float_as_uint(w1.y);
            }
            #pragma unroll
            for (int mi = 0; mi < 4; mi++)
                #pragma unroll
                for (int g = 0; g < 4; g++) {
                    mma_tf32(acc[mi][g][0], acc[mi][g][1], acc[mi][g][2], acc[mi][g][3],
                             ah[mi][0], ah[mi][1], ah[mi][2], ah[mi][3],
                             bl[g][0], bl[g][1]);
                    mma_tf32(acc[mi][g][0], acc[mi][g][1], acc[mi][g][2], acc[mi][g][3],
                             al[mi][0], al[mi][1], al[mi][2], al[mi][3],
                             bh[g][0], bh[g][1]);
                    mma_tf32(acc[mi][g][0], acc[mi][g][1], acc[mi][g][2], acc[mi][g][3],
                             ah[mi][0], ah[mi][1], ah[mi][2], ah[mi][3],
                             bh[g][0], bh[g][1]);
                }
        }
    }

    // Epilogue: bias + tf32 round + scatter (q plain / k d-permuted / vt).
    #pragma unroll
    for (int g = 0; g < 4; g++) {
        const int col = n0 + wn * 32 + g * 8 + (p << 1);   // even
        const int sec = col / CEMB;
        const int nn  = col - sec * CEMB;
        const int hh  = nn >> 6;
        const int d   = nn & 63;
        const float2 bv = *(const float2*)(bias + col);
        #pragma unroll
        for (int mi = 0; mi < 4; mi++) {
            const int row = m0 + wm * 64 + mi * 16 + q;
            #pragma unroll
            for (int half = 0; half < 2; half++) {
                const int rr = row + half * 8;
                const int b = rr >> 11;
                const int t = rr & 2047;
                const int bhh = b * HN + hh;
                const float v0 = __uint_as_float(f2tf32(acc[mi][g][half * 2 + 0] + bv.x));
                const float v1 = __uint_as_float(f2tf32(acc[mi][g][half * 2 + 1] + bv.y));
                if (sec == 0) {
                    *(float2*)&g_q[((size_t)bhh * TDIM + t) * HD + d] = make_float2(v0, v1);
                } else if (sec == 1) {
                    float* base = g_k + ((size_t)bhh * TDIM + t) * HD;
                    base[permd(d)]     = v0;
                    base[permd(d + 1)] = v1;
                } else {
                    const int tp = (t & ~7) | perm8(t & 7);
                    g_vt[((size_t)bhh * HD + d)     * TDIM + tp] = v0;
                    g_vt[((size_t)bhh * HD + d + 1) * TDIM + tp] = v1;
                }
            }
        }
    }
}

// ---------------------------------------------------------------------------
// Kernel 2: causal ReLU attention (mma.sync m16n8k8 tf32). q-tile 128 rows,
// 8 warps. K (d-permuted) + Vt (transposed, t-permuted) -> every B-fragment
// is one float2 LDS.64. THREE-stage cp.async pipeline, ONE barrier per tile.
// ---------------------------------------------------------------------------
__global__ __launch_bounds__(256, 2)
void attn_kernel(float* __restrict__ out)
{
    extern __shared__ __align__(16) float smem[];

    const int tid  = threadIdx.x;
    const int w    = tid >> 5;
    const int lane = tid & 31;
    const int p    = lane & 3;
    const int q    = lane >> 2;

    const int bh = blockIdx.y;
    const int b  = bh / HN;
    const int h  = bh - b * HN;
    const int itile = 15 - blockIdx.x;            // heavy tiles first
    const int jm = 2 * itile + 1;                 // last key tile (inclusive)

    const float* Qg = g_q + ((size_t)bh * TDIM + itile * 128) * HD;
    const float* Kg = g_k + (size_t)bh * TDIM * HD;
    const float* Vg = g_vt + (size_t)bh * HD * TDIM;

    const uint32_t smem_u = (uint32_t)__cvta_generic_to_shared(smem);

    // Q fragments: 8 k-chunks x 4 regs (tf32 values, unpermuted layout)
    uint32_t Qf[8][4];
    {
        const int r0 = (w << 4) + q;
        #pragma unroll
        for (int s = 0; s < 8; s++) {
            const int c0 = (s << 3) + p;
            Qf[s][0] = __float_as_uint(Qg[r0 * 64 + c0]);
            Qf[s][1] = __float_as_uint(Qg[(r0 + 8) * 64 + c0]);
            Qf[s][2] = __float_as_uint(Qg[r0 * 64 + c0 + 4]);
            Qf[s][3] = __float_as_uint(Qg[(r0 + 8) * 64 + c0 + 4]);
        }
    }

    float yacc[8][4];
    #pragma unroll
    for (int g = 0; g < 8; g++)
        #pragma unroll
        for (int r = 0; r < 4; r++)
            yacc[g][r] = 0.0f;

    // stage loader: K tile j (rows=keys) + V tile j (rows=d, cols=t slice)
    auto load_stage = [&](int j, int sbuf) {
        const uint32_t kd = smem_u + (uint32_t)(sbuf * BUF_F) * 4;
        const uint32_t vd = kd + TILE_F * 4;
        const float* Ksrc = Kg + j * 4096;
        const float* Vsrc = Vg + j * 64;
        #pragma unroll
        for (int i = 0; i < 4; i++) {
            const int f = (tid + (i << 8)) << 2;
            const int row = f >> 6, col = f & 63;
            const uint32_t off = (uint32_t)(row * KVS + col) << 2;
            cpa16(kd + off, Ksrc + f);
            cpa16(vd + off, Vsrc + (size_t)row * TDIM + col);
        }
        asm volatile("cp.async.commit_group;");
    };

    // prologue: stages 0 and 1 (jm >= 1 always)
    load_stage(0, 0);
    load_stage(1, 1);

    int cbuf = 0, lbuf = 2;
    const int tw = itile * 128 + (w << 4);        // warp's min query row

    for (int j = 0; j <= jm; j++) {
        if (j < jm) asm volatile("cp.async.wait_group 1;");
        else        asm volatile("cp.async.wait_group 0;");
        __syncthreads();

        if (j + 2 <= jm) {
            load_stage(j + 2, lbuf);
            lbuf = (lbuf == 2) ? 0 : lbuf + 1;
        }

        const float* Kb = smem + cbuf * BUF_F;
        const float* Vb = Kb + TILE_F;
        cbuf = (cbuf == 2) ? 0 : cbuf + 1;

        // GEMM1: S = Q * K^T
        float S[8][4];
        #pragma unroll
        for (int g = 0; g < 8; g++)
            #pragma unroll
            for (int r = 0; r < 4; r++)
                S[g][r] = 0.0f;

        #pragma unroll
        for (int s = 0; s < 8; s++) {
            #pragma unroll
            for (int g = 0; g < 8; g++) {
                const float2 kk =
                    *(const float2*)&Kb[((g << 3) + q) * KVS + (s << 3) + (p << 1)];
                mma_tf32(S[g][0], S[g][1], S[g][2], S[g][3],
                         Qf[s][0], Qf[s][1], Qf[s][2], Qf[s][3],
                         __float_as_uint(kk.x), __float_as_uint(kk.y));
            }
        }

        // scale + relu (+ causal mask on diagonal-straddling tiles), tf32 round
        const bool need_mask = ((j << 6) + 63) > tw;   // warp-uniform
        uint32_t Sb[8][4];
        #pragma unroll
        for (int g = 0; g < 8; g++) {
            float v0 = fmaxf(S[g][0] * 0.125f, 0.0f);
            float v1 = fmaxf(S[g][1] * 0.125f, 0.0f);
            float v2 = fmaxf(S[g][2] * 0.125f, 0.0f);
            float v3 = fmaxf(S[g][3] * 0.125f, 0.0f);
            if (need_mask) {
                const int row0 = tw + q;
                const int col0 = (j << 6) + (g << 3) + (p << 1);
                if (col0     > row0)     v0 = 0.0f;
                if (col0 + 1 > row0)     v1 = 0.0f;
                if (col0     > row0 + 8) v2 = 0.0f;
                if (col0 + 1 > row0 + 8) v3 = 0.0f;
            }
            Sb[g][0] = f2tf32(v0);
            Sb[g][1] = f2tf32(v1);
            Sb[g][2] = f2tf32(v2);
            Sb[g][3] = f2tf32(v3);
        }

        // GEMM2: Y += S * V  (accum layout -> A-frag layout via shfl)
        const int src0 = (lane & ~3) + (p >> 1);
        const int src2 = src0 + 2;
        const bool odd = (p & 1);
        #pragma unroll
        for (int s = 0; s < 8; s++) {
            const uint32_t t00 = __shfl_sync(0xffffffffu, Sb[s][0], src0);
            const uint32_t t01 = __shfl_sync(0xffffffffu, Sb[s][1], src0);
            const uint32_t t20 = __shfl_sync(0xffffffffu, Sb[s][2], src0);
            const uint32_t t21 = __shfl_sync(0xffffffffu, Sb[s][3], src0);
            const uint32_t u00 = __shfl_sync(0xffffffffu, Sb[s][0], src2);
            const uint32_t u01 = __shfl_sync(0xffffffffu, Sb[s][1], src2);
            const uint32_t u20 = __shfl_sync(0xffffffffu, Sb[s][2], src2);
            const uint32_t u21 = __shfl_sync(0xffffffffu, Sb[s][3], src2);
            const uint32_t a0 = odd ? t01 : t00;
            const uint32_t a1 = odd ? t21 : t20;
            const uint32_t a2 = odd ? u01 : u00;
            const uint32_t a3 = odd ? u21 : u20;

            #pragma unroll
            for (int g = 0; g < 8; g++) {
                const float2 vv =
                    *(const float2*)&Vb[((g << 3) + q) * KVS + (s << 3) + (p << 1)];
                mma_tf32(yacc[g][0], yacc[g][1], yacc[g][2], yacc[g][3],
                         a0, a1, a2, a3,
                         __float_as_uint(vv.x), __float_as_uint(vv.y));
            }
        }
    }

    // epilogue: out[b][t][h*64+d]
    const int t0 = itile * 128 + (w << 4) + q;
    const int d0 = h * 64 + (p << 1);
    #pragma unroll
    for (int g = 0; g < 8; g++) {
        float* o0 = out + ((size_t)(b * TDIM + t0)) * CEMB + d0 + (g << 3);
        float* o1 = out + ((size_t)(b * TDIM + t0 + 8)) * CEMB + d0 + (g << 3);
        o0[0] = yacc[g][0];
        o0[1] = yacc[g][1];
        o1[0] = yacc[g][2];
        o1[1] = yacc[g][3];
    }
}

// ---------------------------------------------------------------------------
extern "C" void kernel_launch(void* const* d_in, const int* in_sizes, int n_in,
                              void* d_out, int out_size)
{
    const float* x    = (const float*)d_in[0];   // (4,2048,768)
    const float* w    = (const float*)d_in[1];   // (768,2304)
    const float* bias = (const float*)d_in[2];   // (2304,)
    float* out = (float*)d_out;                  // (4,2048,768)

    cudaFuncSetAttribute(qkv_mma_kernel, cudaFuncAttributeMaxDynamicSharedMemorySize,
                         QKV_SMEM);
    cudaFuncSetAttribute(attn_kernel, cudaFuncAttributeMaxDynamicSharedMemorySize,
                         ATTN_SMEM);

    const int ntot = NX + NW;
    split_kernel<<<(ntot + 255) / 256, 256>>>(x, w);

    dim3 g1(N3C / 128, (CB * TDIM) / 128);       // (18, 64)
    qkv_mma_kernel<<<g1, 256, QKV_SMEM>>>(bias);

    dim3 g2(TDIM / 128, BH);                     // (16, 48)
    attn_kernel<<<g2, 256, ATTN_SMEM>>>(out);
}

// round 16
// speedup vs baseline: 1.0434x; 1.0434x over previous
#include <cuda_runtime.h>
#include <cstdint>

#define TDIM 2048
#define CB 4
#define HN 12
#define HD 64
#define BH (CB*HN)
#define CEMB 768
#define N3C 2304

// ---- attention smem (3-stage) ----
#define KVS 72                             // smem row stride (floats)
#define TILE_F (64 * KVS)                  // 4608
#define BUF_F (2 * TILE_F)                 // K + V, one stage = 9216 floats
#define ATTN_SMEM (3 * BUF_F * 4)          // 110592 B

// ---- qkv mma smem (K-tile 16, hi/lo interleaved, 3-stage) ----
#define SAQ 40                             // A row stride: 32 data + 8 pad
#define SBW 264                            // W row stride: 256 data + 8 pad
#define QSTAGE (128*SAQ + 16*SBW)          // 9344 floats per stage
#define QKV_SMEM (3 * QSTAGE * 4)          // 112128 B

#define NX (8192 * CEMB)
#define NW (CEMB * N3C)

// Pre-split inputs: interleaved (hi,lo) tf32 pairs.
__device__ __align__(16) float g_xs[(size_t)NX * 2];
__device__ __align__(16) float g_ws[(size_t)NW * 2];

// q: (B,H,T,D) plain. k: (B,H,T,D) with D permuted [0,4,1,5,2,6,3,7] per
// 8-group (for GEMM1 B-fragment float2 loads). vt: (B,H,D,T) transposed,
// T PLAIN (GEMM2 feeds S-accum regs directly as A via (d0,d2,d1,d3) reorder,
// which maps hw-k u -> true-k perm8(u); unpermuted V rows line up exactly).
__device__ __align__(16) float g_q[(size_t)BH * TDIM * HD];
__device__ __align__(16) float g_k[(size_t)BH * TDIM * HD];
__device__ __align__(16) float g_vt[(size_t)BH * HD * TDIM];

__device__ __forceinline__ int perm8(int u) { return ((u & 3) << 1) | ((u >> 2) & 1); }
__device__ __forceinline__ int permd(int d) { return (d & ~7) | perm8(d & 7); }

__device__ __forceinline__ uint32_t f2tf32(float x) {
    uint32_t u;
    asm("cvt.rna.tf32.f32 %0, %1;" : "=r"(u) : "f"(x));
    return u;
}

__device__ __forceinline__ void mma_tf32(float& d0, float& d1, float& d2, float& d3,
                                         uint32_t a0, uint32_t a1, uint32_t a2, uint32_t a3,
                                         uint32_t b0, uint32_t b1) {
    asm volatile("mma.sync.aligned.m16n8k8.row.col.f32.tf32.tf32.f32 "
                 "{%0,%1,%2,%3}, {%4,%5,%6,%7}, {%8,%9}, {%0,%1,%2,%3};"
                 : "+f"(d0), "+f"(d1), "+f"(d2), "+f"(d3)
                 : "r"(a0), "r"(a1), "r"(a2), "r"(a3), "r"(b0), "r"(b1));
}

__device__ __forceinline__ void cpa16(uint32_t dst, const float* src) {
    asm volatile("cp.async.cg.shared.global [%0], [%1], 16;" :: "r"(dst), "l"(src));
}

// ---------------------------------------------------------------------------
// Kernel 0: split x and W into interleaved tf32 (hi, lo) pairs.
// ---------------------------------------------------------------------------
__global__ __launch_bounds__(256)
void split_kernel(const float* __restrict__ x, const float* __restrict__ w)
{
    const int i = blockIdx.x * blockDim.x + threadIdx.x;
    if (i < NX) {
        const float v = x[i];
        const uint32_t hi = f2tf32(v);
        const uint32_t lo = f2tf32(v - __uint_as_float(hi));
        *(float2*)&g_xs[(size_t)i * 2] =
            make_float2(__uint_as_float(hi), __uint_as_float(lo));
    }
    const int j = i - NX;
    if (j >= 0 && j < NW) {
        const float v = w[j];
        const uint32_t hi = f2tf32(v);
        const uint32_t lo = f2tf32(v - __uint_as_float(hi));
        *(float2*)&g_ws[(size_t)j * 2] =
            make_float2(__uint_as_float(hi), __uint_as_float(lo));
    }
}

// ---------------------------------------------------------------------------
// Kernel 1: QKV GEMM, 3xTF32 with pre-split operands. 128x128 block tile,
// K-tile 16, 8 warps each 64x32, three-stage cp.async pipeline, one barrier
// per k-tile.
// ---------------------------------------------------------------------------
__global__ __launch_bounds__(256, 2)
void qkv_mma_kernel(const float* __restrict__ bias)
{
    extern __shared__ __align__(16) float sm[];

    const int tid  = threadIdx.x;
    const int w    = tid >> 5;
    const int lane = tid & 31;
    const int p    = lane & 3;
    const int q    = lane >> 2;
    const int wm   = w >> 2;          // 0..1  (64-row slab)
    const int wn   = w & 3;           // 0..3  (32-col slab)

    const int m0 = blockIdx.y << 7;
    const int n0 = blockIdx.x << 7;

    const uint32_t smu = (uint32_t)__cvta_generic_to_shared(sm);

    float acc[4][4][4];
    #pragma unroll
    for (int mi = 0; mi < 4; mi++)
        #pragma unroll
        for (int g = 0; g < 4; g++)
            #pragma unroll
            for (int r = 0; r < 4; r++)
                acc[mi][g][r] = 0.0f;

    // stage loader: per thread 4 float4 for A, 4 for W.
    auto load_stage = [&](int kt, int sbuf) {
        const int kb = kt << 4;
        const uint32_t sb = smu + (uint32_t)(sbuf * QSTAGE) * 4;
        #pragma unroll
        for (int i = 0; i < 4; i++) {
            const int idx = tid + (i << 8);
            const int arow = idx >> 3, acol = (idx & 7) << 2;     // A: 32 f/row
            const int krow = idx >> 6, wcol = (idx & 63) << 2;    // W: 256 f/row
            cpa16(sb + (uint32_t)(arow * SAQ + acol) * 4,
                  g_xs + (size_t)(m0 + arow) * (CEMB * 2) + kb * 2 + acol);
            cpa16(sb + (uint32_t)(128 * SAQ + krow * SBW + wcol) * 4,
                  g_ws + (size_t)(kb + krow) * (N3C * 2) + n0 * 2 + wcol);
        }
        asm volatile("cp.async.commit_group;");
    };

    // prologue: stages 0 and 1
    load_stage(0, 0);
    load_stage(1, 1);

    int cbuf = 0, lbuf = 2;
    for (int kt = 0; kt < 48; kt++) {
        if (kt < 47) asm volatile("cp.async.wait_group 1;");
        else         asm volatile("cp.async.wait_group 0;");
        __syncthreads();

        if (kt + 2 < 48) {
            load_stage(kt + 2, lbuf);
            lbuf = (lbuf == 2) ? 0 : lbuf + 1;
        }

        const float* As = sm + cbuf * QSTAGE;
        const float* Ws = As + 128 * SAQ;
        cbuf = (cbuf == 2) ? 0 : cbuf + 1;

        #pragma unroll
        for (int kc = 0; kc < 16; kc += 8) {
            uint32_t ah[4][4], al[4][4], bh[4][2], bl[4][2];
            #pragma unroll
            for (int mi = 0; mi < 4; mi++) {
                const int base = (wm * 64 + mi * 16 + q) * SAQ + ((kc + p) << 1);
                const float2 f0 = *(const float2*)&As[base];
                const float2 f1 = *(const float2*)&As[base + 8 * SAQ];
                const float2 f2 = *(const float2*)&As[base + 8];
                const float2 f3 = *(const float2*)&As[base + 8 * SAQ + 8];
                ah[mi][0] = __float_as_uint(f0.x); al[mi][0] = __float_as_uint(f0.y);
                ah[mi][1] = __float_as_uint(f1.x); al[mi][1] = __float_as_uint(f1.y);
                ah[mi][2] = __float_as_uint(f2.x); al[mi][2] = __float_as_uint(f2.y);
                ah[mi][3] = __float_as_uint(f3.x); al[mi][3] = __float_as_uint(f3.y);
            }
            #pragma unroll
            for (int g = 0; g < 4; g++) {
                const int bb = (kc + p) * SBW + ((wn * 32 + g * 8 + q) << 1);
                const float2 w0 = *(const float2*)&Ws[bb];
                const float2 w1 = *(const float2*)&Ws[bb + 4 * SBW];
                bh[g][0] = __float_as_uint(w0.x); bl[g][0] = __float_as_uint(w0.y);
                bh[g][1] = __float_as_uint(w1.x); bl[g][1] = __float_as_uint(w1.y);
            }
            #pragma unroll
            for (int mi = 0; mi < 4; mi++)
                #pragma unroll
                for (int g = 0; g < 4; g++) {
                    mma_tf32(acc[mi][g][0], acc[mi][g][1], acc[mi][g][2], acc[mi][g][3],
                             ah[mi][0], ah[mi][1], ah[mi][2], ah[mi][3],
                             bl[g][0], bl[g][1]);
                    mma_tf32(acc[mi][g][0], acc[mi][g][1], acc[mi][g][2], acc[mi][g][3],
                             al[mi][0], al[mi][1], al[mi][2], al[mi][3],
                             bh[g][0], bh[g][1]);
                    mma_tf32(acc[mi][g][0], acc[mi][g][1], acc[mi][g][2], acc[mi][g][3],
                             ah[mi][0], ah[mi][1], ah[mi][2], ah[mi][3],
                             bh[g][0], bh[g][1]);
                }
        }
    }

    // Epilogue: bias + tf32 round + scatter (q plain / k d-permuted / vt plain-t).
    #pragma unroll
    for (int g = 0; g < 4; g++) {
        const int col = n0 + wn * 32 + g * 8 + (p << 1);   // even
        const int sec = col / CEMB;
        const int nn  = col - sec * CEMB;
        const int hh  = nn >> 6;
        const int d   = nn & 63;
        const float2 bv = *(const float2*)(bias + col);
        #pragma unroll
        for (int mi = 0; mi < 4; mi++) {
            const int row = m0 + wm * 64 + mi * 16 + q;
            #pragma unroll
            for (int half = 0; half < 2; half++) {
                const int rr = row + half * 8;
                const int b = rr >> 11;
                const int t = rr & 2047;
                const int bhh = b * HN + hh;
                const float v0 = __uint_as_float(f2tf32(acc[mi][g][half * 2 + 0] + bv.x));
                const float v1 = __uint_as_float(f2tf32(acc[mi][g][half * 2 + 1] + bv.y));
                if (sec == 0) {
                    *(float2*)&g_q[((size_t)bhh * TDIM + t) * HD + d] = make_float2(v0, v1);
                } else if (sec == 1) {
                    float* base = g_k + ((size_t)bhh * TDIM + t) * HD;
                    base[permd(d)]     = v0;
                    base[permd(d + 1)] = v1;
                } else {
                    // vt: t stored PLAIN (no perm8) — GEMM2 A-reg reorder covers it
                    g_vt[((size_t)bhh * HD + d)     * TDIM + t] = v0;
                    g_vt[((size_t)bhh * HD + d + 1) * TDIM + t] = v1;
                }
            }
        }
    }
}

// ---------------------------------------------------------------------------
// Kernel 2: causal ReLU attention (mma.sync m16n8k8 tf32). q-tile 128 rows,
// 8 warps. GEMM2 feeds the S accumulator registers DIRECTLY as A fragments
// in the order (d0,d2,d1,d3) — no shfl fix-up. scale folded into Q at load
// (exact power of 2). Three-stage cp.async pipeline, one barrier per tile.
// ---------------------------------------------------------------------------
__global__ __launch_bounds__(256, 2)
void attn_kernel(float* __restrict__ out)
{
    extern __shared__ __align__(16) float smem[];

    const int tid  = threadIdx.x;
    const int w    = tid >> 5;
    const int lane = tid & 31;
    const int p    = lane & 3;
    const int q    = lane >> 2;

    const int bh = blockIdx.y;
    const int b  = bh / HN;
    const int h  = bh - b * HN;
    const int itile = 15 - blockIdx.x;            // heavy tiles first
    const int jm = 2 * itile + 1;                 // last key tile (inclusive)

    const float* Qg = g_q + ((size_t)bh * TDIM + itile * 128) * HD;
    const float* Kg = g_k + (size_t)bh * TDIM * HD;
    const float* Vg = g_vt + (size_t)bh * HD * TDIM;

    const uint32_t smem_u = (uint32_t)__cvta_generic_to_shared(smem);

    // Q fragments, pre-scaled by 1/sqrt(64)=0.125 (exact on tf32 values)
    uint32_t Qf[8][4];
    {
        const int r0 = (w << 4) + q;
        #pragma unroll
        for (int s = 0; s < 8; s++) {
            const int c0 = (s << 3) + p;
            Qf[s][0] = __float_as_uint(0.125f * Qg[r0 * 64 + c0]);
            Qf[s][1] = __float_as_uint(0.125f * Qg[(r0 + 8) * 64 + c0]);
            Qf[s][2] = __float_as_uint(0.125f * Qg[r0 * 64 + c0 + 4]);
            Qf[s][3] = __float_as_uint(0.125f * Qg[(r0 + 8) * 64 + c0 + 4]);
        }
    }

    float yacc[8][4];
    #pragma unroll
    for (int g = 0; g < 8; g++)
        #pragma unroll
        for (int r = 0; r < 4; r++)
            yacc[g][r] = 0.0f;

    // stage loader: K tile j (rows=keys) + V tile j (rows=d, cols=t slice)
    auto load_stage = [&](int j, int sbuf) {
        const uint32_t kd = smem_u + (uint32_t)(sbuf * BUF_F) * 4;
        const uint32_t vd = kd + TILE_F * 4;
        const float* Ksrc = Kg + j * 4096;
        const float* Vsrc = Vg + j * 64;
        #pragma unroll
        for (int i = 0; i < 4; i++) {
            const int f = (tid + (i << 8)) << 2;
            const int row = f >> 6, col = f & 63;
            const uint32_t off = (uint32_t)(row * KVS + col) << 2;
            cpa16(kd + off, Ksrc + f);
            cpa16(vd + off, Vsrc + (size_t)row * TDIM + col);
        }
        asm volatile("cp.async.commit_group;");
    };

    // prologue: stages 0 and 1 (jm >= 1 always)
    load_stage(0, 0);
    load_stage(1, 1);

    int cbuf = 0, lbuf = 2;
    const int tw = itile * 128 + (w << 4);        // warp's min query row

    for (int j = 0; j <= jm; j++) {
        if (j < jm) asm volatile("cp.async.wait_group 1;");
        else        asm volatile("cp.async.wait_group 0;");
        __syncthreads();

        if (j + 2 <= jm) {
            load_stage(j + 2, lbuf);
            lbuf = (lbuf == 2) ? 0 : lbuf + 1;
        }

        const float* Kb = smem + cbuf * BUF_F;
        const float* Vb = Kb + TILE_F;
        cbuf = (cbuf == 2) ? 0 : cbuf + 1;

        // GEMM1: S = (scale*Q) * K^T
        float S[8][4];
        #pragma unroll
        for (int g = 0; g < 8; g++)
            #pragma unroll
            for (int r = 0; r < 4; r++)
                S[g][r] = 0.0f;

        #pragma unroll
        for (int s = 0; s < 8; s++) {
            #pragma unroll
            for (int g = 0; g < 8; g++) {
                const float2 kk =
                    *(const float2*)&Kb[((g << 3) + q) * KVS + (s << 3) + (p << 1)];
                mma_tf32(S[g][0], S[g][1], S[g][2], S[g][3],
                         Qf[s][0], Qf[s][1], Qf[s][2], Qf[s][3],
                         __float_as_uint(kk.x), __float_as_uint(kk.y));
            }
        }

        // relu (+ causal mask on diagonal-straddling tiles), tf32 round
        const bool need_mask = ((j << 6) + 63) > tw;   // warp-uniform
        uint32_t Sb[8][4];
        #pragma unroll
        for (int g = 0; g < 8; g++) {
            float v0 = fmaxf(S[g][0], 0.0f);
            float v1 = fmaxf(S[g][1], 0.0f);
            float v2 = fmaxf(S[g][2], 0.0f);
            float v3 = fmaxf(S[g][3], 0.0f);
            if (need_mask) {
                const int row0 = tw + q;
                const int col0 = (j << 6) + (g << 3) + (p << 1);
                if (col0     > row0)     v0 = 0.0f;
                if (col0 + 1 > row0)     v1 = 0.0f;
                if (col0     > row0 + 8) v2 = 0.0f;
                if (col0 + 1 > row0 + 8) v3 = 0.0f;
            }
            Sb[g][0] = f2tf32(v0);
            Sb[g][1] = f2tf32(v1);
            Sb[g][2] = f2tf32(v2);
            Sb[g][3] = f2tf32(v3);
        }

        // GEMM2: Y += S * V. Feed accumulator regs directly as A fragment:
        // (a0,a1,a2,a3) = (d0,d2,d1,d3). Rows align; hw-k u maps to true-k
        // perm8(u), matched by reading unpermuted V at col (s*8 + 2p, +1).
        #pragma unroll
        for (int s = 0; s < 8; s++) {
            #pragma unroll
            for (int g = 0; g < 8; g++) {
                const float2 vv =
                    *(const float2*)&Vb[((g << 3) + q) * KVS + (s << 3) + (p << 1)];
                mma_tf32(yacc[g][0], yacc[g][1], yacc[g][2], yacc[g][3],
                         Sb[s][0], Sb[s][2], Sb[s][1], Sb[s][3],
                         __float_as_uint(vv.x), __float_as_uint(vv.y));
            }
        }
    }

    // epilogue: out[b][t][h*64+d]
    const int t0 = itile * 128 + (w << 4) + q;
    const int d0 = h * 64 + (p << 1);
    #pragma unroll
    for (int g = 0; g < 8; g++) {
        float* o0 = out + ((size_t)(b * TDIM + t0)) * CEMB + d0 + (g << 3);
        float* o1 = out + ((size_t)(b * TDIM + t0 + 8)) * CEMB + d0 + (g << 3);
        o0[0] = yacc[g][0];
        o0[1] = yacc[g][1];
        o1[0] = yacc[g][2];
        o1[1] = yacc[g][3];
    }
}

// ---------------------------------------------------------------------------
extern "C" void kernel_launch(void* const* d_in, const int* in_sizes, int n_in,
                              void* d_out, int out_size)
{
    const float* x    = (const float*)d_in[0];   // (4,2048,768)
    const float* w    = (const float*)d_in[1];   // (768,2304)
    const float* bias = (const float*)d_in[2];   // (2304,)
    float* out = (float*)d_out;                  // (4,2048,768)

    cudaFuncSetAttribute(qkv_mma_kernel, cudaFuncAttributeMaxDynamicSharedMemorySize,
                         QKV_SMEM);
    cudaFuncSetAttribute(attn_kernel, cudaFuncAttributeMaxDynamicSharedMemorySize,
                         ATTN_SMEM);

    const int ntot = NX + NW;
    split_kernel<<<(ntot + 255) / 256, 256>>>(x, w);

    dim3 g1(N3C / 128, (CB * TDIM) / 128);       // (18, 64)
    qkv_mma_kernel<<<g1, 256, QKV_SMEM>>>(bias);

    dim3 g2(TDIM / 128, BH);                     // (16, 48)
    attn_kernel<<<g2, 256, ATTN_SMEM>>>(out);
}